// round 3
// baseline (speedup 1.0000x reference)
#include <cuda_runtime.h>
#include <cuda_bf16.h>

// X[16,1024,2], Y[16,1024,8] -> out = [grid(4096,2), Y_grid(16,4096,9)]
// Separable Gaussian: K[(i,j),n] = A[i,n]*B[j,n], exps generated in-kernel.
#define NB     16
#define NN     1024
#define NAX    64
#define NC     9
#define STEP   (6.0f / 63.0f)
#define NSPLIT 8
#define NPER   (NN / NSPLIT)     // 128
#define CN     64                // n-chunk (2 chunks per CTA)
#define NCTA   (NB * 8 * NSPLIT) // 1024 = b*64 + jt*8 + ns
#define EX2C   (-2.885390081777927f)   // -2 * log2(e)

// partials: [cta][c(9)][t(256)] as u64 (packed f32x2 over j-pair)
__device__ unsigned long long g_part[NCTA * 9 * 256];

#define FMA2(d, a, b, c) \
    asm("fma.rn.f32x2 %0, %1, %2, %3;" : "=l"(d) : "l"(a), "l"(b), "l"(c))
#define MUL2(d, a, b) \
    asm("mul.rn.f32x2 %0, %1, %2;" : "=l"(d) : "l"(a), "l"(b))
#define ADD2(d, a, b) \
    asm("add.rn.f32x2 %0, %1, %2;" : "=l"(d) : "l"(a), "l"(b))
#define EX2(d, a) \
    asm("ex2.approx.ftz.f32 %0, %1;" : "=f"(d) : "f"(a))

// ---------- Main: fused exp-gen + partial 3-way contraction ----------
// blockIdx = b*64 + jt*8 + ns. Threads 256: i = t&63, jg = t>>6 (j pair).
__global__ __launch_bounds__(256, 5)
void rkhs_main_kernel(const float* __restrict__ X, const float* __restrict__ Y)
{
    const int bx = blockIdx.x;
    const int ns = bx & 7;
    const int jt = (bx >> 3) & 7;
    const int b  = bx >> 6;

    __shared__ __align__(16) float2 sX[NPER];        // 1 KB
    __shared__ __align__(16) float2 sA2[CN * 64];    // 32 KB  [nn][ii] = (a,a)
    __shared__ __align__(16) float  sBf[CN * 8];     // 2 KB   [nn][jl]
    __shared__ __align__(16) float2 sY[CN * 10];     // 5 KB   [nn][c] = (y,y)

    const int t  = threadIdx.x;
    const int i  = t & 63;
    const int jg = t >> 6;

    if (t < NPER)
        sX[t] = ((const float2*)X)[b * NN + ns * NPER + t];

    const float li  = -3.0f + (float)i * STEP;
    const float lj0 = -3.0f + (float)(jt * 8 + jg * 2) * STEP; // unused in gen, kept simple
    (void)lj0;

    unsigned long long acc[9];
#pragma unroll
    for (int c = 0; c < 9; ++c) acc[c] = 0ULL;

    const float* Yb = Y + b * (NN * 8);

    for (int ch = 0; ch < NPER / CN; ++ch) {
        const int n0  = ns * NPER + ch * CN;   // global n base
        const int nl0 = ch * CN;               // index into sX
        __syncthreads();   // protect smem from previous chunk's readers

        // gen sA2: 64ii x 64nn, thread: ii = i fixed, nn = jg + 4k
#pragma unroll
        for (int k = 0; k < 16; ++k) {
            int nn = jg + k * 4;
            float d = li - sX[nl0 + nn].x;
            float e; EX2(e, d * d * EX2C);
            sA2[nn * 64 + i] = make_float2(e, e);
        }
        // gen sBf: 64nn x 8jl
#pragma unroll
        for (int k = 0; k < 2; ++k) {
            int idx = t + k * 256;
            int jl = idx & 7, nn = idx >> 3;
            float lj = -3.0f + (float)(jt * 8 + jl) * STEP;
            float d = lj - sX[nl0 + nn].y;
            float e; EX2(e, d * d * EX2C);
            sBf[nn * 8 + jl] = e;
        }
        // gen sY: [nn][c] = (v,v), c: 0->1.0, 1..8->Y, 9->pad
        for (int idx = t; idx < CN * 10; idx += 256) {
            int nn = idx / 10;
            int cc = idx - nn * 10;
            float v = 0.0f;
            if (cc == 0)     v = 1.0f;
            else if (cc < 9) v = Yb[(n0 + nn) * 8 + cc - 1];
            sY[nn * 10 + cc] = make_float2(v, v);
        }
        __syncthreads();

        // inner: 17 issue slots / 18 MACs per n
#pragma unroll 8
        for (int nn = 0; nn < CN; ++nn) {
            unsigned long long aa = *(const unsigned long long*)&sA2[nn * 64 + i];
            unsigned long long bp = *(const unsigned long long*)&sBf[nn * 8 + jg * 2];
            unsigned long long pp;
            MUL2(pp, aa, bp);                    // (a*b_j0, a*b_j1)
            const ulonglong2* yr = (const ulonglong2*)&sY[nn * 10];
            ulonglong2 y01 = yr[0];
            ulonglong2 y23 = yr[1];
            ulonglong2 y45 = yr[2];
            ulonglong2 y67 = yr[3];
            unsigned long long y8 = *(const unsigned long long*)&sY[nn * 10 + 8];
            FMA2(acc[0], pp, y01.x, acc[0]);
            FMA2(acc[1], pp, y01.y, acc[1]);
            FMA2(acc[2], pp, y23.x, acc[2]);
            FMA2(acc[3], pp, y23.y, acc[3]);
            FMA2(acc[4], pp, y45.x, acc[4]);
            FMA2(acc[5], pp, y45.y, acc[5]);
            FMA2(acc[6], pp, y67.x, acc[6]);
            FMA2(acc[7], pp, y67.y, acc[7]);
            FMA2(acc[8], pp, y8,    acc[8]);
        }
    }

    // store partials, lane-contiguous u64
    unsigned long long* gp = g_part + (size_t)bx * 9 * 256 + t;
#pragma unroll
    for (int c = 0; c < 9; ++c) gp[c * 256] = acc[c];
}

// ---------- Reduce: sum 8 splits, normalize, write; also grid coords ----------
__global__ __launch_bounds__(256)
void rkhs_reduce_kernel(float* __restrict__ out)
{
    const int rb = blockIdx.x;          // 0..127 = b*8 + jt
    const int t  = threadIdx.x;

    int gtid = rb * 256 + t;
    if (gtid < 4096) {
        int gi = gtid >> 6, gj = gtid & 63;
        out[gtid * 2 + 0] = -3.0f + (float)gi * STEP;
        out[gtid * 2 + 1] = -3.0f + (float)gj * STEP;
    }

    const int b = rb >> 3, jt = rb & 7;

    unsigned long long acc[9];
#pragma unroll
    for (int c = 0; c < 9; ++c) acc[c] = 0ULL;

#pragma unroll
    for (int ns = 0; ns < NSPLIT; ++ns) {
        const unsigned long long* gp =
            g_part + (size_t)(b * 64 + jt * 8 + ns) * 9 * 256 + t;
#pragma unroll
        for (int c = 0; c < 9; ++c) {
            unsigned long long v = gp[c * 256];
            ADD2(acc[c], acc[c], v);
        }
    }

    const int i = t & 63, jg = t >> 6;
    const int j0 = jt * 8 + jg * 2;

    float lo[9], hi[9];
#pragma unroll
    for (int c = 0; c < 9; ++c)
        asm("mov.b64 {%0, %1}, %2;" : "=f"(lo[c]), "=f"(hi[c]) : "l"(acc[c]));

    float r0 = 1.0f / (lo[0] + 1e-6f);
    float r1 = 1.0f / (hi[0] + 1e-6f);

    float* o = out + 8192 + (size_t)(b * 4096 + i * 64 + j0) * NC;
    o[0] = lo[0];
#pragma unroll
    for (int c = 1; c < 9; ++c) o[c] = lo[c] * r0;
    o[NC] = hi[0];
#pragma unroll
    for (int c = 1; c < 9; ++c) o[NC + c] = hi[c] * r1;
}

extern "C" void kernel_launch(void* const* d_in, const int* in_sizes, int n_in,
                              void* d_out, int out_size)
{
    const float* X = (const float*)d_in[0];
    const float* Y = (const float*)d_in[1];
    float* out = (float*)d_out;

    rkhs_main_kernel<<<NCTA, 256>>>(X, Y);
    rkhs_reduce_kernel<<<128, 256>>>(out);
}

// round 4
// speedup vs baseline: 1.0086x; 1.0086x over previous
#include <cuda_runtime.h>

// X[16,1024,2], Y[16,1024,8] -> out = [grid(4096,2), Y_grid(16,4096,9)]
// Single fused kernel. CTA = (b, it, jt): i-tile 16, j-tile 8. Grid 512.
// 256 threads = 64 slots (8 i-pairs x 8 j) x 4 n-quarters (256 n each).
// Accumulators: f32x2 packed over adjacent i (A pair-packed, B/Y duplicated).

#define NN    1024
#define STEP  (6.0f / 63.0f)
#define EX2C  (-2.885390081777927f)   // -2 * log2(e)
#define CN    32                      // n-chunk per quarter per stage

// smem offsets (bytes) inside one raw buffer; epilogue regions overlap tiles
#define OFF_SX   0                    // float2[1024]            : 8192
#define OFF_SA   8192                 // u64 [4][32][8]  (A i-pairs)  : 8192
#define OFF_SB   16384                // u64 [4][32][8]  (B dup)      : 8192
#define OFF_SY   24576                // u64 [4][32][10] (Y dup)      : 10240
#define SMEM_SZ  34816
#define OFF_RED  0                    // u64 [64][4][9]          : 18432 (reuse)
#define OFF_OUT  18944                // float[16][8][9]         : 4608  (reuse)

#define FMA2(d, a, b, c) \
    asm("fma.rn.f32x2 %0, %1, %2, %3;" : "=l"(d) : "l"(a), "l"(b), "l"(c))
#define MUL2(d, a, b) \
    asm("mul.rn.f32x2 %0, %1, %2;" : "=l"(d) : "l"(a), "l"(b))
#define ADD2(d, a, b) \
    asm("add.rn.f32x2 %0, %1, %2;" : "=l"(d) : "l"(a), "l"(b))
#define EX2(d, a) \
    asm("ex2.approx.ftz.f32 %0, %1;" : "=f"(d) : "f"(a))
#define UNPK(lo, hi, in) \
    asm("mov.b64 {%0, %1}, %2;" : "=f"(lo), "=f"(hi) : "l"(in))

typedef unsigned long long u64;

__global__ __launch_bounds__(256, 4)
void rkhs_fused_kernel(const float* __restrict__ X, const float* __restrict__ Y,
                       float* __restrict__ out)
{
    __shared__ __align__(16) char smem[SMEM_SZ];

    const int bx = blockIdx.x;
    const int b  = bx >> 5;
    const int it = (bx >> 3) & 3;
    const int jt = bx & 7;

    const int t  = threadIdx.x;
    const int q  = t >> 6;          // n-quarter 0..3
    const int s  = t & 63;          // slot
    const int ip = s & 7;           // i-pair 0..7  (i_local = ip*2, ip*2+1)
    const int jl = s >> 3;          // j 0..7

    // grid coords (first 16 CTAs cover 4096 points)
    if (bx < 16) {
        int p = bx * 256 + t;
        out[p * 2 + 0] = -3.0f + (float)(p >> 6) * STEP;
        out[p * 2 + 1] = -3.0f + (float)(p & 63) * STEP;
    }

    // load whole X[b] into smem
    float2* sX = (float2*)(smem + OFF_SX);
    const float2* Xb = (const float2*)X + b * NN;
#pragma unroll
    for (int k = 0; k < 4; ++k)
        sX[t + k * 256] = Xb[t + k * 256];

    const float* Yb = Y + b * (NN * 8);

    const float li0 = -3.0f + (float)(it * 16 + ip * 2) * STEP;
    const float li1 = li0 + STEP;
    const float lj  = -3.0f + (float)(jt * 8 + jl) * STEP;

    u64 acc[9];
#pragma unroll
    for (int c = 0; c < 9; ++c) acc[c] = 0ULL;

    u64* sA = (u64*)(smem + OFF_SA) + q * (CN * 8);
    u64* sB = (u64*)(smem + OFF_SB) + q * (CN * 8);
    u64* sY = (u64*)(smem + OFF_SY) + q * (CN * 10);

#pragma unroll 1
    for (int ch = 0; ch < 256 / CN; ++ch) {
        const int nbase = q * 256 + ch * CN;
        __syncthreads();

        // stage A: [nn][ip] = (exp(i0,n), exp(i1,n)); 4 entries/thread
#pragma unroll
        for (int k = 0; k < 4; ++k) {
            int e  = s + k * 64;
            int nn = e >> 3, ipp = e & 7;
            float xv = sX[nbase + nn].x;
            float l0 = -3.0f + (float)(it * 16 + ipp * 2) * STEP;
            float d0 = l0 - xv;
            float d1 = d0 + STEP;
            float e0, e1;
            EX2(e0, d0 * d0 * EX2C);
            EX2(e1, d1 * d1 * EX2C);
            float2 v = make_float2(e0, e1);
            sA[nn * 8 + ipp] = *(u64*)&v;
        }
        // stage B dup: [nn][jl] = (e,e)
#pragma unroll
        for (int k = 0; k < 4; ++k) {
            int e  = s + k * 64;
            int nn = e >> 3, jj = e & 7;
            float yv = sX[nbase + nn].y;
            float l  = -3.0f + (float)(jt * 8 + jj) * STEP;
            float d  = l - yv;
            float ev;
            EX2(ev, d * d * EX2C);
            float2 v = make_float2(ev, ev);
            sB[nn * 8 + jj] = *(u64*)&v;
        }
        // stage Y dup: [nn][c]: c0=1, c1..8=Y, c9=0
#pragma unroll
        for (int k = 0; k < 5; ++k) {
            int e = s + k * 64;            // < 320
            int nn = e / 10;
            int c  = e - nn * 10;
            float v = 0.0f;
            if (c == 0)     v = 1.0f;
            else if (c < 9) v = Yb[(nbase + nn) * 8 + c - 1];
            float2 vv = make_float2(v, v);
            sY[nn * 10 + c] = *(u64*)&vv;
        }
        __syncthreads();

        const u64* pA = sA + ip;
        const u64* pB = sB + jl;
#pragma unroll
        for (int nn = 0; nn < CN; ++nn) {
            u64 aa = pA[nn * 8];
            u64 bb = pB[nn * 8];
            u64 pp;
            MUL2(pp, aa, bb);                       // (A_i0*B, A_i1*B)
            const u64* yr = sY + nn * 10;
            ulonglong2 y01 = *(const ulonglong2*)(yr);
            ulonglong2 y23 = *(const ulonglong2*)(yr + 2);
            ulonglong2 y45 = *(const ulonglong2*)(yr + 4);
            ulonglong2 y67 = *(const ulonglong2*)(yr + 6);
            u64 y8 = yr[8];
            FMA2(acc[0], pp, y01.x, acc[0]);
            FMA2(acc[1], pp, y01.y, acc[1]);
            FMA2(acc[2], pp, y23.x, acc[2]);
            FMA2(acc[3], pp, y23.y, acc[3]);
            FMA2(acc[4], pp, y45.x, acc[4]);
            FMA2(acc[5], pp, y45.y, acc[5]);
            FMA2(acc[6], pp, y67.x, acc[6]);
            FMA2(acc[7], pp, y67.y, acc[7]);
            FMA2(acc[8], pp, y8,    acc[8]);
        }
    }

    // ---- intra-CTA reduce over 4 quarters ----
    __syncthreads();
    u64* red = (u64*)(smem + OFF_RED);              // [s][q][9]
    if (q > 0) {
        u64* my = red + (s * 36 + q * 9);
#pragma unroll
        for (int c = 0; c < 9; ++c) my[c] = acc[c];
    }
    __syncthreads();

    float* so = (float*)(smem + OFF_OUT);           // [16][8][9]
    if (t < 64) {
        const u64* rr = red + s * 36;
#pragma unroll
        for (int qq = 1; qq < 4; ++qq)
#pragma unroll
            for (int c = 0; c < 9; ++c)
                ADD2(acc[c], acc[c], rr[qq * 9 + c]);

        float lo[9], hi[9];
#pragma unroll
        for (int c = 0; c < 9; ++c) UNPK(lo[c], hi[c], acc[c]);

        float r0 = 1.0f / (lo[0] + 1e-6f);
        float r1 = 1.0f / (hi[0] + 1e-6f);

        int base0 = ((ip * 2) * 8 + jl) * 9;
        int base1 = base0 + 72;                     // next i row
        so[base0] = lo[0];
        so[base1] = hi[0];
#pragma unroll
        for (int c = 1; c < 9; ++c) {
            so[base0 + c] = lo[c] * r0;
            so[base1 + c] = hi[c] * r1;
        }
    }
    __syncthreads();

    // coalesced-ish store of 1152 floats
    const size_t obase = 8192 + (size_t)b * 4096 * 9;
#pragma unroll
    for (int k = 0; k < 5; ++k) {
        int idx = t + k * 256;
        if (idx < 1152) {
            int il  = idx / 72;
            int rem = idx - il * 72;
            int jj  = rem / 9;
            int c   = rem - jj * 9;
            out[obase + (size_t)((it * 16 + il) * 64 + jt * 8 + jj) * 9 + c] = so[idx];
        }
    }
}

extern "C" void kernel_launch(void* const* d_in, const int* in_sizes, int n_in,
                              void* d_out, int out_size)
{
    const float* X = (const float*)d_in[0];
    const float* Y = (const float*)d_in[1];
    float* out = (float*)d_out;

    rkhs_fused_kernel<<<512, 256>>>(X, Y, out);
}

// round 5
// speedup vs baseline: 1.7984x; 1.7831x over previous
#include <cuda_runtime.h>
#include <cstdint>

// out[b,i,j,c] = sum_k exp(-2(li-x0k)^2) * exp(-2(lj-x1k)^2) * Yb[k,c]
// GEMM form: C[64i x 640(jc)] = A[64 x 1024] * Z[1024 x 640], tf32 mma.sync.
#define NB    16
#define NN    1024
#define STEP  (6.0f / 63.0f)
#define EX2C  (-2.885390081777927f)   // -2 * log2(e)
#define KC    64
#define NCHUNK (NN / KC)              // 16

// A pre-permuted to m16n8k8 a-frag layout: [b][kc16][k8 8][slab4][lane32][quad4]
__device__ uint32_t g_Aperm[NB * NN * 64];

__device__ __forceinline__ uint32_t cvt_tf32(float f) {
    uint32_t r;
    asm("cvt.rna.tf32.f32 %0, %1;" : "=r"(r) : "f"(f));
    return r;
}
__device__ __forceinline__ float ex2f(float x) {
    float r; asm("ex2.approx.ftz.f32 %0, %1;" : "=f"(r) : "f"(x)); return r;
}

#define MMA_TF32(d, a, bb) \
    asm volatile("mma.sync.aligned.m16n8k8.row.col.f32.tf32.tf32.f32 " \
        "{%0,%1,%2,%3}, {%4,%5,%6,%7}, {%8,%9}, {%0,%1,%2,%3};" \
        : "+f"(d[0]), "+f"(d[1]), "+f"(d[2]), "+f"(d[3]) \
        : "r"(a.x), "r"(a.y), "r"(a.z), "r"(a.w), "r"(bb.x), "r"(bb.y))

// ---------- precompute: A (tf32, frag-permuted) + grid coords ----------
__global__ __launch_bounds__(256)
void rkhs_precomp_kernel(const float* __restrict__ X, float* __restrict__ out)
{
    int tid = blockIdx.x * blockDim.x + threadIdx.x;

    if (tid < 4096) {
        out[tid * 2 + 0] = -3.0f + (float)(tid >> 6) * STEP;
        out[tid * 2 + 1] = -3.0f + (float)(tid & 63) * STEP;
    }

    const int TOT = NB * NN * 64;       // 1,048,576
    int stride = gridDim.x * blockDim.x;
    for (int idx = tid; idx < TOT; idx += stride) {
        int q    = idx & 3;
        int lane = (idx >> 2) & 31;
        int slab = (idx >> 7) & 3;
        int k8   = (idx >> 9) & 7;
        int kc   = (idx >> 12) & 15;
        int b    = idx >> 16;
        int m = slab * 16 + (lane >> 2) + ((q & 1) << 3);
        int k = kc * KC + k8 * 8 + (lane & 3) + ((q >> 1) << 2);
        float li = -3.0f + (float)m * STEP;
        float xv = X[(b * NN + k) * 2];          // x0
        float d  = li - xv;
        g_Aperm[idx] = cvt_tf32(ex2f(d * d * EX2C));
    }
}

// ---------- main: tf32 mma GEMM, 256 CTAs = b(16) x jt(16) ----------
// CTA: M=64 (all i), N=40 (4 j x 10 c), K=1024 in 16 chunks of 64.
// 256 thr = 8 warps: slab = wid&3 (16 rows), nh = wid>>2 (ncols {0,1,2} / {3,4}).
#define SM_A 0          // u32[4096] = 16KB  (aliased by sD[64][40] f32 in epilogue)
#define SM_Z 16384      // u32[8][5][32][2] = 10240
#define SM_Y 26624      // float[64][8]     = 2048
#define SM_B 28672      // float[4][64]     = 1024
#define SM_TOT 29696

__global__ __launch_bounds__(256)
void rkhs_mma_kernel(const float* __restrict__ X, const float* __restrict__ Y,
                     float* __restrict__ out)
{
    __shared__ __align__(16) char smem[SM_TOT];
    uint32_t* sA = (uint32_t*)(smem + SM_A);
    uint32_t* sZ = (uint32_t*)(smem + SM_Z);
    float*    sY = (float*)(smem + SM_Y);
    float*    sB = (float*)(smem + SM_B);

    const int b  = blockIdx.x >> 4;
    const int jt = blockIdx.x & 15;

    const int t    = threadIdx.x;
    const int lane = t & 31;
    const int wid  = t >> 5;
    const int slab = wid & 3;
    const int nh   = wid >> 2;
    const int nc0  = nh * 3;               // first ncol
    const int ncnt = nh ? 2 : 3;           // ncols this warp owns

    float acc[3][4];
#pragma unroll
    for (int a = 0; a < 3; ++a)
#pragma unroll
        for (int r = 0; r < 4; ++r) acc[a][r] = 0.0f;

    const float* Yb = Y + b * (NN * 8);
    const uint32_t* gA = g_Aperm + (size_t)b * (NCHUNK * 4096);

    for (int kc = 0; kc < NCHUNK; ++kc) {
        const int k0 = kc * KC;
        __syncthreads();

        // stage Y chunk: [64 k][8 c], float4 x128
        if (t < 128) {
            int kk = t >> 1, h = t & 1;
            ((float4*)sY)[t] = *(const float4*)(Yb + (k0 + kk) * 8 + h * 4);
        }
        // stage Bexp: [4 j][64 k]
        {
            int j = t >> 6, kk = t & 63;
            float xv = X[(b * NN + k0 + kk) * 2 + 1];   // x1
            float lj = -3.0f + (float)(jt * 4 + j) * STEP;
            float d  = lj - xv;
            sB[j * KC + kk] = ex2f(d * d * EX2C);
        }
        // stage A chunk: straight copy of 4096 u32 (already permuted)
        {
            const uint4* src = (const uint4*)(gA + kc * 4096);
            uint4* dst = (uint4*)sA;
#pragma unroll
            for (int r = 0; r < 4; ++r)
                dst[t + r * 256] = src[t + r * 256];
        }
        __syncthreads();   // sB ready before Z build reads it

        // build Z frag-permuted: [k8 8][ncol 5][lane 32][2]
#pragma unroll
        for (int rep = 0; rep < 5; ++rep) {
            int grp = rep * 8 + wid;              // 0..39 = k8*5 + nc
            int k8g = grp / 5;
            int nc  = grp - k8g * 5;
            int kk  = k8g * 8 + (lane & 3);       // k within chunk (and +4)
            int n   = nc * 8 + (lane >> 2);
            int jl  = n / 10;
            int c   = n - jl * 10;
            float y0, y1;
            if (c == 0)      { y0 = 1.0f; y1 = 1.0f; }
            else if (c == 9) { y0 = 0.0f; y1 = 0.0f; }
            else {
                y0 = sY[kk * 8 + (c - 1)];
                y1 = sY[(kk + 4) * 8 + (c - 1)];
            }
            float b0 = sB[jl * KC + kk];
            float b1 = sB[jl * KC + kk + 4];
            uint2 z;
            z.x = cvt_tf32(b0 * y0);
            z.y = cvt_tf32(b1 * y1);
            *(uint2*)(sZ + ((k8g * 5 + nc) * 32 + lane) * 2) = z;
        }
        __syncthreads();

        // mma mainloop
#pragma unroll
        for (int k8 = 0; k8 < 8; ++k8) {
            uint4 a = *(const uint4*)(sA + ((k8 * 4 + slab) * 32 + lane) * 4);
#pragma unroll
            for (int cc = 0; cc < 3; ++cc) {
                if (cc < ncnt) {
                    uint2 bb = *(const uint2*)(sZ + ((k8 * 5 + nc0 + cc) * 32 + lane) * 2);
                    MMA_TF32(acc[cc], a, bb);
                }
            }
        }
    }

    // ---- epilogue: accs -> smem [64][40], divide, store ----
    __syncthreads();
    float* sD = (float*)(smem + SM_A);     // alias A region
#pragma unroll
    for (int cc = 0; cc < 3; ++cc) {
        if (cc < ncnt) {
            int col = (nc0 + cc) * 8 + (lane & 3) * 2;
            int row = slab * 16 + (lane >> 2);
            sD[row * 40 + col]           = acc[cc][0];
            sD[row * 40 + col + 1]       = acc[cc][1];
            sD[(row + 8) * 40 + col]     = acc[cc][2];
            sD[(row + 8) * 40 + col + 1] = acc[cc][3];
        }
    }
    __syncthreads();

    // 2304 outputs: o -> (i, j, c)
#pragma unroll
    for (int rep = 0; rep < 9; ++rep) {
        int o = t + rep * 256;
        int i   = o / 36;
        int rem = o - i * 36;
        int j   = rem / 9;
        int c   = rem - j * 9;
        float dens = sD[i * 40 + j * 10];
        float v = (c == 0) ? dens : sD[i * 40 + j * 10 + c] / (dens + 1e-6f);
        out[8192 + (size_t)((b * 4096) + i * 64 + (jt * 4 + j)) * 9 + c] = v;
    }
}

extern "C" void kernel_launch(void* const* d_in, const int* in_sizes, int n_in,
                              void* d_out, int out_size)
{
    const float* X = (const float*)d_in[0];
    const float* Y = (const float*)d_in[1];
    float* out = (float*)d_out;

    rkhs_precomp_kernel<<<1024, 256>>>(X, out);
    rkhs_mma_kernel<<<256, 256>>>(X, Y, out);
}

// round 6
// speedup vs baseline: 1.9120x; 1.0632x over previous
#include <cuda_runtime.h>
#include <cstdint>

// out[b,i,j,c] = sum_k exp(-2(li-x0k)^2)*exp(-2(lj-x1k)^2)*Yb[k,c]
// GEMM: C[64 x 640] = A[64 x 1024] * Z[1024 x 640] (Z = B (x) Yb), tf32 mma.
#define NB    16
#define NN    1024
#define STEP  (6.0f / 63.0f)
#define EX2C  (-2.885390081777927f)   // -2*log2(e)
#define KC    64

// A in m16n8k8 a-frag layout: [b][kc16][k8 8][slab4][lane32][quad4]
__device__ uint32_t g_Aperm[NB * NN * 64];
// partials in c-frag layout: [ks2][b*16+jt][nc5][slab4][lane32][4]
__device__ float g_part[2 * 256 * 2560];

__device__ __forceinline__ uint32_t cvt_tf32(float f) {
    uint32_t r; asm("cvt.rna.tf32.f32 %0, %1;" : "=r"(r) : "f"(f)); return r;
}
__device__ __forceinline__ float ex2f(float x) {
    float r; asm("ex2.approx.ftz.f32 %0, %1;" : "=f"(r) : "f"(x)); return r;
}
#define MMA_TF32(d, a, bb) \
    asm volatile("mma.sync.aligned.m16n8k8.row.col.f32.tf32.tf32.f32 " \
        "{%0,%1,%2,%3}, {%4,%5,%6,%7}, {%8,%9}, {%0,%1,%2,%3};" \
        : "+f"(d[0]), "+f"(d[1]), "+f"(d[2]), "+f"(d[3]) \
        : "r"(a.x), "r"(a.y), "r"(a.z), "r"(a.w), "r"(bb.x), "r"(bb.y))

// ---------- precompute A (tf32, frag-permuted) + grid coords ----------
__global__ __launch_bounds__(256)
void rkhs_precomp_kernel(const float* __restrict__ X, float* __restrict__ out)
{
    int tid = blockIdx.x * blockDim.x + threadIdx.x;
    if (tid < 4096) {
        out[tid * 2 + 0] = -3.0f + (float)(tid >> 6) * STEP;
        out[tid * 2 + 1] = -3.0f + (float)(tid & 63) * STEP;
    }
    const int TOT = NB * NN * 64;
    int stride = gridDim.x * blockDim.x;
    for (int idx = tid; idx < TOT; idx += stride) {
        int q    = idx & 3;
        int lane = (idx >> 2) & 31;
        int slab = (idx >> 7) & 3;
        int k8   = (idx >> 9) & 7;
        int kc   = (idx >> 12) & 15;
        int b    = idx >> 16;
        int m = slab * 16 + (lane >> 2) + ((q & 1) << 3);
        int k = kc * KC + k8 * 8 + (lane & 3) + ((q >> 1) << 2);
        float li = -3.0f + (float)m * STEP;
        float d  = li - X[(b * NN + k) * 2];
        g_Aperm[idx] = cvt_tf32(ex2f(d * d * EX2C));
    }
}

// ---------- main: grid 512 = b(16) x jt(16) x ks(2), 256 thr ----------
#define SMZ 0          // u32 [8k8][5nc][32lane][2] = 10240 B
#define SMY 10240      // float[64][8] = 2048
#define SMB 12288      // float[4][64] = 1024
#define SMT 13312

__global__ __launch_bounds__(256, 3)
void rkhs_mma_kernel(const float* __restrict__ X, const float* __restrict__ Y)
{
    __shared__ __align__(16) char smem[SMT];
    uint32_t* sZ = (uint32_t*)(smem + SMZ);
    float*    sY = (float*)(smem + SMY);
    float*    sB = (float*)(smem + SMB);

    const int bx = blockIdx.x;
    const int ks = bx & 1;
    const int jt = (bx >> 1) & 15;
    const int b  = bx >> 5;

    const int t    = threadIdx.x;
    const int lane = t & 31;
    const int wid  = t >> 5;
    const int slab = wid & 3;
    const int nh   = wid >> 2;
    const int nc0  = nh * 3;
    const int ncnt = nh ? 2 : 3;

    // hoisted Z-build constants (5 reps)
    int zslot[5], bidx[5], yidx[5], ymode[5];   // ymode: 0=Y, 1=one, 2=zero
#pragma unroll
    for (int rep = 0; rep < 5; ++rep) {
        int grp = rep * 8 + wid;
        int k8g = grp / 5;
        int nc  = grp - k8g * 5;
        int kk  = k8g * 8 + (lane & 3);
        int n   = nc * 8 + (lane >> 2);
        int jl  = n / 10;
        int c   = n - jl * 10;
        zslot[rep] = ((k8g * 5 + nc) * 32 + lane) * 2;
        bidx[rep]  = jl * KC + kk;
        yidx[rep]  = (c >= 1 && c <= 8) ? kk * 8 + (c - 1) : 0;
        ymode[rep] = (c == 0) ? 1 : ((c == 9) ? 2 : 0);
    }

    float acc[3][4];
#pragma unroll
    for (int a = 0; a < 3; ++a)
#pragma unroll
        for (int r = 0; r < 4; ++r) acc[a][r] = 0.0f;

    const float* Yb = Y + b * (NN * 8);
    const uint4* gA = (const uint4*)g_Aperm + (size_t)b * 16384 + ks * 8192
                      + slab * 32 + lane;
    const float ljs = -3.0f + (float)(jt * 4 + (t >> 6)) * STEP;  // sB stage lj
    const int   bkk = t & 63;                                      // sB stage k
    const float* Xb1 = X + b * NN * 2 + 1;

    for (int ch = 0; ch < 8; ++ch) {
        const int k0 = ks * 512 + ch * KC;

        // prefetch A frags for this chunk (consumed after 2 barriers)
        uint4 af[8];
#pragma unroll
        for (int k8 = 0; k8 < 8; ++k8)
            af[k8] = __ldg(gA + ch * 1024 + k8 * 128);

        // stage Y: [64k][8c]
        if (t < 128)
            ((float4*)sY)[t] = *(const float4*)(Yb + (k0 + (t >> 1)) * 8 + (t & 1) * 4);
        // stage B: [4j][64k]
        {
            float d = ljs - Xb1[(k0 + bkk) * 2];
            sB[(t >> 6) * KC + bkk] = ex2f(d * d * EX2C);
        }
        __syncthreads();   // staging visible; prev-chunk mma done (sZ safe)

        // build Z (frag-permuted)
#pragma unroll
        for (int rep = 0; rep < 5; ++rep) {
            float b0 = sB[bidx[rep]];
            float b1 = sB[bidx[rep] + 4];
            float y0, y1;
            if (ymode[rep] == 0) { y0 = sY[yidx[rep]]; y1 = sY[yidx[rep] + 32]; }
            else if (ymode[rep] == 1) { y0 = 1.0f; y1 = 1.0f; }
            else { y0 = 0.0f; y1 = 0.0f; }
            uint2 z;
            z.x = cvt_tf32(b0 * y0);
            z.y = cvt_tf32(b1 * y1);
            *(uint2*)(sZ + zslot[rep]) = z;
        }
        __syncthreads();

        // mma
#pragma unroll
        for (int k8 = 0; k8 < 8; ++k8) {
#pragma unroll
            for (int cc = 0; cc < 3; ++cc) {
                if (cc < ncnt) {
                    uint2 bb = *(const uint2*)(sZ + ((k8 * 5 + nc0 + cc) * 32 + lane) * 2);
                    MMA_TF32(acc[cc], af[k8], bb);
                }
            }
        }
    }

    // store partials in frag layout, coalesced ST.128
    float* gp = g_part + ((size_t)(ks * 256 + b * 16 + jt)) * 2560;
#pragma unroll
    for (int cc = 0; cc < 3; ++cc) {
        if (cc < ncnt) {
            float4 v = make_float4(acc[cc][0], acc[cc][1], acc[cc][2], acc[cc][3]);
            *(float4*)(gp + (((nc0 + cc) * 4 + slab) * 32 + lane) * 4) = v;
        }
    }
}

// ---------- reduce: sum 2 K-splits, normalize, write ----------
__global__ __launch_bounds__(256)
void rkhs_reduce_kernel(float* __restrict__ out)
{
    __shared__ float sD[2560];
    const int cb = blockIdx.x;          // b*16 + jt
    const int b  = cb >> 4;
    const int jt = cb & 15;
    const int t  = threadIdx.x;

    const float* p0 = g_part + (size_t)cb * 2560;
    const float* p1 = g_part + (size_t)(256 + cb) * 2560;
#pragma unroll
    for (int k = 0; k < 10; ++k) {
        int idx = t + k * 256;
        sD[idx] = p0[idx] + p1[idx];
    }
    __syncthreads();

#pragma unroll
    for (int rep = 0; rep < 9; ++rep) {
        int o = t + rep * 256;
        if (o < 2304) {
            int i   = o / 36;
            int rem = o - i * 36;
            int j   = rem / 9;
            int c   = rem - j * 9;
            int slab = i >> 4, rr = i & 15, half = rr >> 3, r8 = rr & 7;
            int col  = j * 10 + c;
            int idx  = (((col >> 3) * 4 + slab) * 32 + r8 * 4 + ((col & 7) >> 1)) * 4
                       + half * 2 + (col & 1);
            int colD = j * 10;
            int idxD = (((colD >> 3) * 4 + slab) * 32 + r8 * 4 + ((colD & 7) >> 1)) * 4
                       + half * 2 + (colD & 1);
            float dens = sD[idxD];
            float v = (c == 0) ? dens : sD[idx] / (dens + 1e-6f);
            out[8192 + (size_t)(b * 4096 + i * 64 + jt * 4 + j) * 9 + c] = v;
        }
    }
}

extern "C" void kernel_launch(void* const* d_in, const int* in_sizes, int n_in,
                              void* d_out, int out_size)
{
    const float* X = (const float*)d_in[0];
    const float* Y = (const float*)d_in[1];
    float* out = (float*)d_out;

    rkhs_precomp_kernel<<<1024, 256>>>(X, out);
    rkhs_mma_kernel<<<512, 256>>>(X, Y);
    rkhs_reduce_kernel<<<256, 256>>>(out);
}

// round 7
// speedup vs baseline: 2.4975x; 1.3063x over previous
#include <cuda_runtime.h>
#include <cstdint>

// out[b,i,j,c] = sum_k exp(-2(li-x0k)^2)*exp(-2(lj-x1k)^2)*Yb[k,c]
// GEMM: C[64 x 640] = A[64 x 1024] * Z[1024 x 640], bf16 mma m16n8k16.
#define NB    16
#define NN    1024
#define STEP  (6.0f / 63.0f)
#define EX2C  (-2.885390081777927f)   // -2*log2(e)
#define KC    64

// A in m16n8k16 a-frag layout, bf16x2 packed:
// [b][kstep 64][slab 4][lane 32][q 4] u32;  q: (row+8*(q&1), kcol+8*(q>>1))
__device__ __align__(16) uint32_t g_Aperm[NB * 64 * 4 * 32 * 4];
// partials in c-frag layout: [ks2][b*16+jt][nc5][slab4][lane32][4]
__device__ __align__(16) float g_part[2 * 256 * 2560];

__device__ __forceinline__ float ex2f(float x) {
    float r; asm("ex2.approx.ftz.f32 %0, %1;" : "=f"(r) : "f"(x)); return r;
}
// pack (lo, hi) -> bf16x2 (PTX: second src is lo half)
__device__ __forceinline__ uint32_t pack_bf16(float lo, float hi) {
    uint32_t d;
    asm("cvt.rn.bf16x2.f32 %0, %1, %2;" : "=r"(d) : "f"(hi), "f"(lo));
    return d;
}
#define MMA_BF16(d, a, bb) \
    asm volatile("mma.sync.aligned.m16n8k16.row.col.f32.bf16.bf16.f32 " \
        "{%0,%1,%2,%3}, {%4,%5,%6,%7}, {%8,%9}, {%0,%1,%2,%3};" \
        : "+f"(d[0]), "+f"(d[1]), "+f"(d[2]), "+f"(d[3]) \
        : "r"(a.x), "r"(a.y), "r"(a.z), "r"(a.w), "r"(bb.x), "r"(bb.y))

// ---------- precompute A (bf16x2 frag-packed) + grid coords ----------
__global__ __launch_bounds__(256)
void rkhs_precomp_kernel(const float* __restrict__ X, float* __restrict__ out)
{
    int tid = blockIdx.x * blockDim.x + threadIdx.x;
    if (tid < 4096) {
        out[tid * 2 + 0] = -3.0f + (float)(tid >> 6) * STEP;
        out[tid * 2 + 1] = -3.0f + (float)(tid & 63) * STEP;
    }
    const int TOT = NB * 64 * 4 * 32 * 4;      // 524288
    int stride = gridDim.x * blockDim.x;
    for (int idx = tid; idx < TOT; idx += stride) {
        int q     = idx & 3;
        int lane  = (idx >> 2) & 31;
        int slab  = (idx >> 7) & 3;
        int kstep = (idx >> 9) & 63;
        int b     = idx >> 15;
        int row = slab * 16 + (lane >> 2) + ((q & 1) << 3);
        int kb  = kstep * 16 + ((lane & 3) << 1) + ((q >> 1) << 3);
        float4 xx = *(const float4*)(X + (size_t)(b * NN + kb) * 2); // x0[kb], x1[kb], x0[kb+1], x1[kb+1]
        float li = -3.0f + (float)row * STEP;
        float d0 = li - xx.x;
        float d1 = li - xx.z;
        g_Aperm[idx] = pack_bf16(ex2f(d0 * d0 * EX2C), ex2f(d1 * d1 * EX2C));
    }
}

// ---------- main: grid 512 = b(16) x jt(16) x ks(2), 256 thr ----------
#define YSTR 66
__global__ __launch_bounds__(256, 4)
void rkhs_mma_kernel(const float* __restrict__ X, const float* __restrict__ Y)
{
    __shared__ __align__(16) uint32_t sZ[4 * 5 * 32 * 2];   // 5120 B, bf16x2
    __shared__ __align__(16) float    sYt[8 * YSTR];        // [c][k], pad 66
    __shared__ __align__(16) float    sB[4 * YSTR];         // [j][k], pad 66

    const int bx = blockIdx.x;
    const int ks = bx & 1;
    const int jt = (bx >> 1) & 15;
    const int b  = bx >> 5;

    const int t    = threadIdx.x;
    const int lane = t & 31;
    const int wid  = t >> 5;
    const int slab = wid & 3;
    const int nh   = wid >> 2;
    const int nc0  = nh * 3;
    const int ncnt = nh ? 2 : 3;

    // hoisted Z-build constants: groups = rep*8 + wid, 20 total (kstep4 x nc5)
    int zslot[3], boff[3], yoff[3], ymode[3], gvalid[3];
#pragma unroll
    for (int rep = 0; rep < 3; ++rep) {
        int grp = rep * 8 + wid;
        gvalid[rep] = (grp < 20);
        int g = gvalid[rep] ? grp : 0;
        int kst = g / 5;
        int nc  = g - kst * 5;
        int klo = kst * 16 + ((lane & 3) << 1);
        int n   = nc * 8 + (lane >> 2);
        int jl  = n / 10;
        int c   = n - jl * 10;
        zslot[rep] = ((kst * 5 + nc) * 32 + lane) * 2;
        boff[rep]  = jl * YSTR + klo;
        yoff[rep]  = (c >= 1 && c <= 8) ? (c - 1) * YSTR + klo : 0;
        ymode[rep] = (c == 0) ? 1 : ((c == 9) ? 2 : 0);
    }

    float acc[3][4];
#pragma unroll
    for (int a = 0; a < 3; ++a)
#pragma unroll
        for (int r = 0; r < 4; ++r) acc[a][r] = 0.0f;

    const float* Yb = Y + b * (NN * 8);
    // per b: 8192 uint4; per ks half: 4096; frag idx = (kstep*4+slab)*32+lane
    const uint4* gA = (const uint4*)g_Aperm + (size_t)b * 8192 + ks * 4096
                      + slab * 32 + lane;
    const float ljs = -3.0f + (float)(jt * 4 + (t >> 6)) * STEP;   // B stage
    const int   bkk = t & 63;
    const int   yc  = t & 7;                                        // Y stage
    const int   ykk = t >> 3;
    const float* Xb1 = X + b * NN * 2 + 1;

    for (int ch = 0; ch < 8; ++ch) {
        const int k0 = ks * 512 + ch * KC;

        // prefetch A frags (4 x LDG.128), consumed after 2 barriers
        uint4 af[4];
#pragma unroll
        for (int kst = 0; kst < 4; ++kst)
            af[kst] = __ldg(gA + (ch * 4 + kst) * 128);

        // stage Y transposed: sYt[c][k]
        sYt[yc * YSTR + ykk]      = Yb[(k0 + ykk) * 8 + yc];
        sYt[yc * YSTR + ykk + 32] = Yb[(k0 + ykk + 32) * 8 + yc];
        // stage B: sB[j][k]
        {
            float d = ljs - Xb1[(k0 + bkk) * 2];
            sB[(t >> 6) * YSTR + bkk] = ex2f(d * d * EX2C);
        }
        __syncthreads();   // staging visible; prev-chunk mma done (sZ safe)

        // build Z (bf16x2 frag-packed)
#pragma unroll
        for (int rep = 0; rep < 3; ++rep) {
            if (gvalid[rep]) {
                float2 b0 = *(const float2*)(sB + boff[rep]);       // k, k+1
                float2 b1 = *(const float2*)(sB + boff[rep] + 8);   // k+8, k+9
                uint2 z;
                if (ymode[rep] == 1) {
                    z.x = pack_bf16(b0.x, b0.y);
                    z.y = pack_bf16(b1.x, b1.y);
                } else if (ymode[rep] == 2) {
                    z.x = 0u; z.y = 0u;
                } else {
                    float2 y0 = *(const float2*)(sYt + yoff[rep]);
                    float2 y1 = *(const float2*)(sYt + yoff[rep] + 8);
                    z.x = pack_bf16(b0.x * y0.x, b0.y * y0.y);
                    z.y = pack_bf16(b1.x * y1.x, b1.y * y1.y);
                }
                *(uint2*)(sZ + zslot[rep]) = z;
            }
        }
        __syncthreads();

        // mma: 4 k16-steps x ncnt ncols
#pragma unroll
        for (int kst = 0; kst < 4; ++kst) {
#pragma unroll
            for (int cc = 0; cc < 3; ++cc) {
                if (cc < ncnt) {
                    uint2 bb = *(const uint2*)(sZ + ((kst * 5 + nc0 + cc) * 32 + lane) * 2);
                    MMA_BF16(acc[cc], af[kst], bb);
                }
            }
        }
    }

    // store partials in c-frag layout, ST.128 coalesced
    float* gp = g_part + ((size_t)(ks * 256 + b * 16 + jt)) * 2560;
#pragma unroll
    for (int cc = 0; cc < 3; ++cc) {
        if (cc < ncnt) {
            float4 v = make_float4(acc[cc][0], acc[cc][1], acc[cc][2], acc[cc][3]);
            *(float4*)(gp + (((nc0 + cc) * 4 + slab) * 32 + lane) * 4) = v;
        }
    }
}

// ---------- reduce: sum 2 K-splits, normalize, write ----------
__global__ __launch_bounds__(256)
void rkhs_reduce_kernel(float* __restrict__ out)
{
    __shared__ float sD[2560];
    const int cb = blockIdx.x;          // b*16 + jt
    const int b  = cb >> 4;
    const int jt = cb & 15;
    const int t  = threadIdx.x;

    const float* p0 = g_part + (size_t)cb * 2560;
    const float* p1 = g_part + (size_t)(256 + cb) * 2560;
#pragma unroll
    for (int k = 0; k < 10; ++k) {
        int idx = t + k * 256;
        sD[idx] = p0[idx] + p1[idx];
    }
    __syncthreads();

#pragma unroll
    for (int rep = 0; rep < 9; ++rep) {
        int o = t + rep * 256;
        if (o < 2304) {
            int i   = o / 36;
            int rem = o - i * 36;
            int j   = rem / 9;
            int c   = rem - j * 9;
            int slab = i >> 4, rr = i & 15, half = rr >> 3, r8 = rr & 7;
            int col  = j * 10 + c;
            int idx  = (((col >> 3) * 4 + slab) * 32 + r8 * 4 + ((col & 7) >> 1)) * 4
                       + half * 2 + (col & 1);
            int colD = j * 10;
            int idxD = (((colD >> 3) * 4 + slab) * 32 + r8 * 4 + ((colD & 7) >> 1)) * 4
                       + half * 2 + (colD & 1);
            float dens = sD[idxD];
            float v = (c == 0) ? dens : sD[idx] / (dens + 1e-6f);
            out[8192 + (size_t)(b * 4096 + i * 64 + jt * 4 + j) * 9 + c] = v;
        }
    }
}

extern "C" void kernel_launch(void* const* d_in, const int* in_sizes, int n_in,
                              void* d_out, int out_size)
{
    const float* X = (const float*)d_in[0];
    const float* Y = (const float*)d_in[1];
    float* out = (float*)d_out;

    rkhs_precomp_kernel<<<512, 256>>>(X, out);
    rkhs_mma_kernel<<<512, 256>>>(X, Y);
    rkhs_reduce_kernel<<<256, 256>>>(out);
}

// round 8
// speedup vs baseline: 2.5227x; 1.0101x over previous
#include <cuda_runtime.h>
#include <cstdint>

// out[b,i,j,c] = sum_k exp(-2(li-x0k)^2)*exp(-2(lj-x1k)^2)*Yb[k,c]
// GEMM: C[64 x 640] = A[64 x 1024] * Z[1024 x 640], bf16 mma m16n8k16.
#define NB    16
#define NN    1024
#define STEP  (6.0f / 63.0f)
#define EX2C  (-2.885390081777927f)   // -2*log2(e)
#define KC    64

// A in m16n8k16 a-frag layout, bf16x2 packed:
// [b][kstep 64][slab 4][lane 32][q 4] u32
__device__ __align__(16) uint32_t g_Aperm[NB * 64 * 4 * 32 * 4];
// partials in c-frag layout: [ks2][b*16+jt][nc5][slab4][lane32][4]
__device__ __align__(16) float g_part[2 * 256 * 2560];

__device__ __forceinline__ float ex2f(float x) {
    float r; asm("ex2.approx.ftz.f32 %0, %1;" : "=f"(r) : "f"(x)); return r;
}
__device__ __forceinline__ uint32_t pack_bf16(float lo, float hi) {
    uint32_t d;
    asm("cvt.rn.bf16x2.f32 %0, %1, %2;" : "=r"(d) : "f"(hi), "f"(lo));
    return d;
}
#define MMA_BF16(d, a, bb) \
    asm volatile("mma.sync.aligned.m16n8k16.row.col.f32.bf16.bf16.f32 " \
        "{%0,%1,%2,%3}, {%4,%5,%6,%7}, {%8,%9}, {%0,%1,%2,%3};" \
        : "+f"(d[0]), "+f"(d[1]), "+f"(d[2]), "+f"(d[3]) \
        : "r"(a.x), "r"(a.y), "r"(a.z), "r"(a.w), "r"(bb.x), "r"(bb.y))

// ---------- precompute A (bf16x2 frag-packed) + grid coords ----------
// grid 2048 x 256: exactly one element per thread (no loop -> full occupancy)
__global__ __launch_bounds__(256)
void rkhs_precomp_kernel(const float* __restrict__ X, float* __restrict__ out)
{
    int idx = blockIdx.x * blockDim.x + threadIdx.x;
    if (idx < 4096) {
        out[idx * 2 + 0] = -3.0f + (float)(idx >> 6) * STEP;
        out[idx * 2 + 1] = -3.0f + (float)(idx & 63) * STEP;
    }
    int q     = idx & 3;
    int lane  = (idx >> 2) & 31;
    int slab  = (idx >> 7) & 3;
    int kstep = (idx >> 9) & 63;
    int b     = idx >> 15;
    int row = slab * 16 + (lane >> 2) + ((q & 1) << 3);
    int kb  = kstep * 16 + ((lane & 3) << 1) + ((q >> 1) << 3);
    float4 xx = *(const float4*)(X + (size_t)(b * NN + kb) * 2);
    float li = -3.0f + (float)row * STEP;
    float d0 = li - xx.x;
    float d1 = li - xx.z;
    g_Aperm[idx] = pack_bf16(ex2f(d0 * d0 * EX2C), ex2f(d1 * d1 * EX2C));
}

// ---------- main: grid 512 = b(16) x jt(16) x ks(2), 256 thr ----------
// Double-buffered staging + Z: ONE __syncthreads per chunk.
#define YSTR 66
__global__ __launch_bounds__(256, 4)
void rkhs_mma_kernel(const float* __restrict__ X, const float* __restrict__ Y)
{
    __shared__ __align__(16) uint32_t sZ[2][4 * 5 * 32 * 2];   // 2 x 5120 B
    __shared__ __align__(16) float    sYt[2][8 * YSTR];        // [c][k]
    __shared__ __align__(16) float    sB[2][4 * YSTR];         // [j][k]

    const int bx = blockIdx.x;
    const int ks = bx & 1;
    const int jt = (bx >> 1) & 15;
    const int b  = bx >> 5;

    const int t    = threadIdx.x;
    const int lane = t & 31;
    const int wid  = t >> 5;
    const int slab = wid & 3;
    const int nh   = wid >> 2;
    const int nc0  = nh * 3;
    const int ncnt = nh ? 2 : 3;

    // hoisted Z-build constants (groups = rep*8 + wid, 20 of kstep4 x nc5)
    int zslot[3], boff[3], yoff[3], ymode[3], gvalid[3];
#pragma unroll
    for (int rep = 0; rep < 3; ++rep) {
        int grp = rep * 8 + wid;
        gvalid[rep] = (grp < 20);
        int g = gvalid[rep] ? grp : 0;
        int kst = g / 5;
        int nc  = g - kst * 5;
        int klo = kst * 16 + ((lane & 3) << 1);
        int n   = nc * 8 + (lane >> 2);
        int jl  = n / 10;
        int c   = n - jl * 10;
        zslot[rep] = ((kst * 5 + nc) * 32 + lane) * 2;
        boff[rep]  = jl * YSTR + klo;
        yoff[rep]  = (c >= 1 && c <= 8) ? (c - 1) * YSTR + klo : 0;
        ymode[rep] = (c == 0) ? 1 : ((c == 9) ? 2 : 0);
    }

    float acc[3][4];
#pragma unroll
    for (int a = 0; a < 3; ++a)
#pragma unroll
        for (int r = 0; r < 4; ++r) acc[a][r] = 0.0f;

    const float* Yb = Y + b * (NN * 8);
    const uint4* gA = (const uint4*)g_Aperm + (size_t)b * 8192 + ks * 4096
                      + slab * 32 + lane;
    const float ljs = -3.0f + (float)(jt * 4 + (t >> 6)) * STEP;
    const int   bkk = t & 63;
    const int   yc  = t & 7;
    const int   ykk = t >> 3;
    const float* Xb1 = X + b * NN * 2 + 1;

    // ---- staging helper (macro to keep regs in scope) ----
#define STAGE(buf, kk0)                                                       \
    do {                                                                      \
        sYt[buf][yc * YSTR + ykk]      = Yb[((kk0) + ykk) * 8 + yc];          \
        sYt[buf][yc * YSTR + ykk + 32] = Yb[((kk0) + ykk + 32) * 8 + yc];     \
        float d_ = ljs - Xb1[((kk0) + bkk) * 2];                              \
        sB[buf][(t >> 6) * YSTR + bkk] = ex2f(d_ * d_ * EX2C);                \
    } while (0)

#define BUILDZ(buf)                                                           \
    do {                                                                      \
        _Pragma("unroll")                                                     \
        for (int rep = 0; rep < 3; ++rep) {                                   \
            if (gvalid[rep]) {                                                \
                float2 b0 = *(const float2*)(sB[buf] + boff[rep]);            \
                float2 b1 = *(const float2*)(sB[buf] + boff[rep] + 8);        \
                uint2 z;                                                      \
                if (ymode[rep] == 1) {                                        \
                    z.x = pack_bf16(b0.x, b0.y);                              \
                    z.y = pack_bf16(b1.x, b1.y);                              \
                } else if (ymode[rep] == 2) {                                 \
                    z.x = 0u; z.y = 0u;                                       \
                } else {                                                      \
                    float2 y0 = *(const float2*)(sYt[buf] + yoff[rep]);       \
                    float2 y1 = *(const float2*)(sYt[buf] + yoff[rep] + 8);   \
                    z.x = pack_bf16(b0.x * y0.x, b0.y * y0.y);                \
                    z.y = pack_bf16(b1.x * y1.x, b1.y * y1.y);                \
                }                                                             \
                *(uint2*)(sZ[buf] + zslot[rep]) = z;                          \
            }                                                                 \
        }                                                                     \
    } while (0)

    // prologue: stage chunk 0
    STAGE(0, ks * 512);
    __syncthreads();

#pragma unroll 1
    for (int ch = 0; ch < 8; ++ch) {
        const int p = ch & 1;
        const int k1 = ks * 512 + (ch + 1) * KC;

        // A frags for this chunk (consumed after buildZ + stage + bar)
        uint4 af[4];
#pragma unroll
        for (int kst = 0; kst < 4; ++kst)
            af[kst] = __ldg(gA + (ch * 4 + kst) * 128);

        BUILDZ(p);                       // Z(ch) from staging[p]
        if (ch < 7) STAGE(1 - p, k1);    // stage chunk ch+1
        __syncthreads();

        // mma(ch): reads sZ[p]; next iter writes sZ[1-p] -> safe
#pragma unroll
        for (int kst = 0; kst < 4; ++kst) {
#pragma unroll
            for (int cc = 0; cc < 3; ++cc) {
                if (cc < ncnt) {
                    uint2 bb = *(const uint2*)(sZ[p] + ((kst * 5 + nc0 + cc) * 32 + lane) * 2);
                    MMA_BF16(acc[cc], af[kst], bb);
                }
            }
        }
    }

    // store partials in c-frag layout, ST.128 coalesced
    float* gp = g_part + ((size_t)(ks * 256 + b * 16 + jt)) * 2560;
#pragma unroll
    for (int cc = 0; cc < 3; ++cc) {
        if (cc < ncnt) {
            float4 v = make_float4(acc[cc][0], acc[cc][1], acc[cc][2], acc[cc][3]);
            *(float4*)(gp + (((nc0 + cc) * 4 + slab) * 32 + lane) * 4) = v;
        }
    }
}

// ---------- reduce: sum 2 K-splits, normalize, write ----------
__global__ __launch_bounds__(256)
void rkhs_reduce_kernel(float* __restrict__ out)
{
    __shared__ float sD[2560];
    const int cb = blockIdx.x;
    const int b  = cb >> 4;
    const int jt = cb & 15;
    const int t  = threadIdx.x;

    const float* p0 = g_part + (size_t)cb * 2560;
    const float* p1 = g_part + (size_t)(256 + cb) * 2560;
#pragma unroll
    for (int k = 0; k < 10; ++k) {
        int idx = t + k * 256;
        sD[idx] = p0[idx] + p1[idx];
    }
    __syncthreads();

#pragma unroll
    for (int rep = 0; rep < 9; ++rep) {
        int o = t + rep * 256;
        if (o < 2304) {
            int i   = o / 36;
            int rem = o - i * 36;
            int j   = rem / 9;
            int c   = rem - j * 9;
            int slab = i >> 4, rr = i & 15, half = rr >> 3, r8 = rr & 7;
            int col  = j * 10 + c;
            int idx  = (((col >> 3) * 4 + slab) * 32 + r8 * 4 + ((col & 7) >> 1)) * 4
                       + half * 2 + (col & 1);
            int colD = j * 10;
            int idxD = (((colD >> 3) * 4 + slab) * 32 + r8 * 4 + ((colD & 7) >> 1)) * 4
                       + half * 2 + (colD & 1);
            float dens = sD[idxD];
            float v = (c == 0) ? dens : sD[idx] / (dens + 1e-6f);
            out[8192 + (size_t)(b * 4096 + i * 64 + jt * 4 + j) * 9 + c] = v;
        }
    }
}

extern "C" void kernel_launch(void* const* d_in, const int* in_sizes, int n_in,
                              void* d_out, int out_size)
{
    const float* X = (const float*)d_in[0];
    const float* Y = (const float*)d_in[1];
    float* out = (float*)d_out;

    rkhs_precomp_kernel<<<2048, 256>>>(X, out);
    rkhs_mma_kernel<<<512, 256>>>(X, Y);
    rkhs_reduce_kernel<<<256, 256>>>(out);
}